// round 1
// baseline (speedup 1.0000x reference)
#include <cuda_runtime.h>
#include <cuda_bf16.h>
#include <math.h>

#define NN 100000
#define EE 1600000
#define FD 128
#define HD 64

// Scratch (device globals; no allocation allowed)
__device__ float g_deg[2 * NN];          // [0..N) = deg_out(src), [NN..NN+N) = deg_in(dst)
__device__ float g_nsrc[NN];
__device__ float g_ndst[NN];
__device__ float g_x[(size_t)NN * HD];   // gemm1 output x, later reused as y = relu(...)·nsrc
__device__ float g_agg1[(size_t)NN * HD];
__device__ float g_agg2[(size_t)NN * HD];

// ---------------------------------------------------------------------------
// Degrees
// ---------------------------------------------------------------------------
__global__ void deg_kernel(const int* __restrict__ src, const int* __restrict__ dst, int E) {
    int i = blockIdx.x * blockDim.x + threadIdx.x;
    if (i < E) {
        atomicAdd(&g_deg[src[i]], 1.0f);
        atomicAdd(&g_deg[NN + dst[i]], 1.0f);
    }
}

__global__ void norm_kernel(int N) {
    int i = blockIdx.x * blockDim.x + threadIdx.x;
    if (i < N) {
        g_nsrc[i] = rsqrtf(fmaxf(g_deg[i], 1.0f));
        g_ndst[i] = rsqrtf(fmaxf(g_deg[NN + i], 1.0f));
    }
}

// ---------------------------------------------------------------------------
// GEMM1: x = (feat * nsrc) @ W1    [N,128] x [128,64]
// Block: 256 threads (16x16), tile 64 rows x 64 cols, K chunked 2x64.
// ---------------------------------------------------------------------------
__global__ void __launch_bounds__(256) gemm1_kernel(const float* __restrict__ feat,
                                                    const float* __restrict__ W1, int N) {
    __shared__ float As[64][68];   // stride 68: banks (4r+k)%32, conflict-free
    __shared__ float Ws[64][64];
    int tx = threadIdx.x & 15, ty = threadIdx.x >> 4;
    int r0 = blockIdx.x * 64;

    float acc[4][4] = {};

    for (int k0 = 0; k0 < FD; k0 += 64) {
        // Load A chunk (64 rows x 64 k), scaled by nsrc
        for (int idx = threadIdx.x; idx < 1024; idx += 256) {
            int r = idx >> 4;      // 16 float4 per row
            int c4 = idx & 15;
            int row = r0 + r;
            float4 v = make_float4(0.f, 0.f, 0.f, 0.f);
            float s = 0.f;
            if (row < N) {
                v = *(const float4*)(feat + (size_t)row * FD + k0 + c4 * 4);
                s = g_nsrc[row];
            }
            v.x *= s; v.y *= s; v.z *= s; v.w *= s;
            *(float4*)&As[r][c4 * 4] = v;
        }
        // Load W chunk (rows k0..k0+63 are contiguous)
        for (int idx = threadIdx.x; idx < 1024; idx += 256) {
            ((float4*)Ws)[idx] = ((const float4*)(W1 + (size_t)k0 * HD))[idx];
        }
        __syncthreads();

#pragma unroll
        for (int k = 0; k < 64; k++) {
            float a0 = As[ty * 4 + 0][k];
            float a1 = As[ty * 4 + 1][k];
            float a2 = As[ty * 4 + 2][k];
            float a3 = As[ty * 4 + 3][k];
            float4 w = *(float4*)&Ws[k][tx * 4];
            acc[0][0] += a0 * w.x; acc[0][1] += a0 * w.y; acc[0][2] += a0 * w.z; acc[0][3] += a0 * w.w;
            acc[1][0] += a1 * w.x; acc[1][1] += a1 * w.y; acc[1][2] += a1 * w.z; acc[1][3] += a1 * w.w;
            acc[2][0] += a2 * w.x; acc[2][1] += a2 * w.y; acc[2][2] += a2 * w.z; acc[2][3] += a2 * w.w;
            acc[3][0] += a3 * w.x; acc[3][1] += a3 * w.y; acc[3][2] += a3 * w.z; acc[3][3] += a3 * w.w;
        }
        __syncthreads();
    }

#pragma unroll
    for (int i = 0; i < 4; i++) {
        int row = r0 + ty * 4 + i;
        if (row < N) {
            float4 o = make_float4(acc[i][0], acc[i][1], acc[i][2], acc[i][3]);
            *(float4*)(g_x + (size_t)row * HD + tx * 4) = o;
        }
    }
}

// ---------------------------------------------------------------------------
// Scatter-add: agg[dst] += x[src]  (64 floats per edge, float4 atomics)
// One thread per float4 of one edge: E*16 items.
// ---------------------------------------------------------------------------
__global__ void scatter_kernel(const int* __restrict__ src, const int* __restrict__ dst,
                               const float* __restrict__ x, float* __restrict__ agg, int E) {
    int i = blockIdx.x * blockDim.x + threadIdx.x;
    int total = E * 16;
    if (i < total) {
        int e = i >> 4;
        int j = i & 15;
        int s = src[e];
        int d = dst[e];
        float4 v = *(const float4*)(x + (size_t)s * HD + j * 4);
        atomicAdd((float4*)(agg + (size_t)d * HD + j * 4), v);
    }
}

// ---------------------------------------------------------------------------
// Mid: y = relu(agg1 * ndst + b1) * nsrc   (written back into g_x)
// ---------------------------------------------------------------------------
__global__ void mid_kernel(const float* __restrict__ b1, int N) {
    int i = blockIdx.x * blockDim.x + threadIdx.x;  // N*16 float4 items
    if (i < N * 16) {
        int row = i >> 4;
        int c4 = i & 15;
        float nd = g_ndst[row];
        float ns = g_nsrc[row];
        float4 a = *(float4*)(g_agg1 + (size_t)i * 4);
        float4 b = *(const float4*)(b1 + c4 * 4);
        float4 y;
        y.x = fmaxf(a.x * nd + b.x, 0.f) * ns;
        y.y = fmaxf(a.y * nd + b.y, 0.f) * ns;
        y.z = fmaxf(a.z * nd + b.z, 0.f) * ns;
        y.w = fmaxf(a.w * nd + b.w, 0.f) * ns;
        *(float4*)(g_x + (size_t)i * 4) = y;
    }
}

// ---------------------------------------------------------------------------
// Final: mu = (agg2@W_mu)*ndst + b_mu ; ls = (agg2@W_sig)*ndst + b_sig ;
//        z = mu + noise * exp(ls)
// Tiled dual-GEMM: 64 rows x 128 cols (W_mu | W_sig concatenated), K chunked 2x32.
// ---------------------------------------------------------------------------
__global__ void __launch_bounds__(256) final_kernel(const float* __restrict__ noise,
                                                    const float* __restrict__ W_mu,
                                                    const float* __restrict__ b_mu,
                                                    const float* __restrict__ W_sig,
                                                    const float* __restrict__ b_sig,
                                                    float* __restrict__ out, int N) {
    __shared__ float As[64][36];     // stride 36: banks (4r+k)%32, conflict-free
    __shared__ float Wc[32][128];    // [k][0..63]=W_mu, [k][64..127]=W_sig
    int tx = threadIdx.x & 15, ty = threadIdx.x >> 4;
    int r0 = blockIdx.x * 64;

    float am[4][4] = {};
    float asg[4][4] = {};

    for (int k0 = 0; k0 < HD; k0 += 32) {
        // A chunk: 64 rows x 32 k = 512 float4
        for (int idx = threadIdx.x; idx < 512; idx += 256) {
            int r = idx >> 3;      // 8 float4 per row
            int c4 = idx & 7;
            int row = r0 + r;
            float4 v = make_float4(0.f, 0.f, 0.f, 0.f);
            if (row < N) v = *(const float4*)(g_agg2 + (size_t)row * HD + k0 + c4 * 4);
            *(float4*)&As[r][c4 * 4] = v;
        }
        // W chunk: 32 k x 128 cols = 1024 float4
        for (int idx = threadIdx.x; idx < 1024; idx += 256) {
            int k = idx >> 5;      // 32 float4 per row
            int c4 = idx & 31;
            if (c4 < 16) {
                *(float4*)&Wc[k][c4 * 4] = *(const float4*)(W_mu + (size_t)(k0 + k) * HD + c4 * 4);
            } else {
                *(float4*)&Wc[k][64 + (c4 - 16) * 4] =
                    *(const float4*)(W_sig + (size_t)(k0 + k) * HD + (c4 - 16) * 4);
            }
        }
        __syncthreads();

#pragma unroll
        for (int k = 0; k < 32; k++) {
            float a0 = As[ty * 4 + 0][k];
            float a1 = As[ty * 4 + 1][k];
            float a2 = As[ty * 4 + 2][k];
            float a3 = As[ty * 4 + 3][k];
            float4 wm = *(float4*)&Wc[k][tx * 4];
            float4 ws = *(float4*)&Wc[k][64 + tx * 4];
            am[0][0] += a0 * wm.x; am[0][1] += a0 * wm.y; am[0][2] += a0 * wm.z; am[0][3] += a0 * wm.w;
            am[1][0] += a1 * wm.x; am[1][1] += a1 * wm.y; am[1][2] += a1 * wm.z; am[1][3] += a1 * wm.w;
            am[2][0] += a2 * wm.x; am[2][1] += a2 * wm.y; am[2][2] += a2 * wm.z; am[2][3] += a2 * wm.w;
            am[3][0] += a3 * wm.x; am[3][1] += a3 * wm.y; am[3][2] += a3 * wm.z; am[3][3] += a3 * wm.w;
            asg[0][0] += a0 * ws.x; asg[0][1] += a0 * ws.y; asg[0][2] += a0 * ws.z; asg[0][3] += a0 * ws.w;
            asg[1][0] += a1 * ws.x; asg[1][1] += a1 * ws.y; asg[1][2] += a1 * ws.z; asg[1][3] += a1 * ws.w;
            asg[2][0] += a2 * ws.x; asg[2][1] += a2 * ws.y; asg[2][2] += a2 * ws.z; asg[2][3] += a2 * ws.w;
            asg[3][0] += a3 * ws.x; asg[3][1] += a3 * ws.y; asg[3][2] += a3 * ws.z; asg[3][3] += a3 * ws.w;
        }
        __syncthreads();
    }

    float4 bm = *(const float4*)(b_mu + tx * 4);
    float4 bs = *(const float4*)(b_sig + tx * 4);

#pragma unroll
    for (int i = 0; i < 4; i++) {
        int row = r0 + ty * 4 + i;
        if (row < N) {
            float nd = g_ndst[row];
            float4 nz = *(const float4*)(noise + (size_t)row * HD + tx * 4);
            float4 o;
            o.x = (am[i][0] * nd + bm.x) + nz.x * expf(asg[i][0] * nd + bs.x);
            o.y = (am[i][1] * nd + bm.y) + nz.y * expf(asg[i][1] * nd + bs.y);
            o.z = (am[i][2] * nd + bm.z) + nz.z * expf(asg[i][2] * nd + bs.z);
            o.w = (am[i][3] * nd + bm.w) + nz.w * expf(asg[i][3] * nd + bs.w);
            *(float4*)(out + (size_t)row * HD + tx * 4) = o;
        }
    }
}

// ---------------------------------------------------------------------------
// Launch
// ---------------------------------------------------------------------------
extern "C" void kernel_launch(void* const* d_in, const int* in_sizes, int n_in,
                              void* d_out, int out_size) {
    const float* feat  = (const float*)d_in[0];
    const int*   src   = (const int*)d_in[1];
    const int*   dst   = (const int*)d_in[2];
    const float* noise = (const float*)d_in[3];
    const float* W1    = (const float*)d_in[4];
    const float* b1    = (const float*)d_in[5];
    const float* W_mu  = (const float*)d_in[6];
    const float* b_mu  = (const float*)d_in[7];
    const float* W_sig = (const float*)d_in[8];
    const float* b_sig = (const float*)d_in[9];

    int N = in_sizes[0] / FD;
    int E = in_sizes[1];

    void *p_deg, *p_x, *p_agg1, *p_agg2;
    cudaGetSymbolAddress(&p_deg,  g_deg);
    cudaGetSymbolAddress(&p_x,    g_x);
    cudaGetSymbolAddress(&p_agg1, g_agg1);
    cudaGetSymbolAddress(&p_agg2, g_agg2);

    // Zero scratch (graph-capturable async memsets)
    cudaMemsetAsync(p_deg,  0, sizeof(float) * 2 * NN);
    cudaMemsetAsync(p_agg1, 0, sizeof(float) * (size_t)NN * HD);
    cudaMemsetAsync(p_agg2, 0, sizeof(float) * (size_t)NN * HD);

    deg_kernel<<<(E + 255) / 256, 256>>>(src, dst, E);
    norm_kernel<<<(N + 255) / 256, 256>>>(N);

    gemm1_kernel<<<(N + 63) / 64, 256>>>(feat, W1, N);

    int scat_items = E * 16;
    scatter_kernel<<<(scat_items + 255) / 256, 256>>>(src, dst, (const float*)p_x,
                                                      (float*)p_agg1, E);

    mid_kernel<<<(N * 16 + 255) / 256, 256>>>(b1, N);

    scatter_kernel<<<(scat_items + 255) / 256, 256>>>(src, dst, (const float*)p_x,
                                                      (float*)p_agg2, E);

    final_kernel<<<(N + 63) / 64, 256>>>(noise, W_mu, b_mu, W_sig, b_sig,
                                         (float*)d_out, N);
}

// round 2
// speedup vs baseline: 1.4483x; 1.4483x over previous
#include <cuda_runtime.h>
#include <cuda_bf16.h>
#include <math.h>

#define NN 100000
#define EE 1600000
#define FD 128
#define HD 64
#define SCAN_B 256
#define NBLK ((NN + SCAN_B - 1) / SCAN_B)   // 391

// Scratch (device globals)
__device__ int   g_cnt_out[NN];
__device__ int   g_cnt_in[NN];
__device__ float g_nsrc[NN];
__device__ float g_ndst[NN];
__device__ int   g_bsum[512];              // block partial sums / offsets
__device__ int   g_off[NN + 1];            // CSR row offsets (by dst)
__device__ int   g_cursor[NN];
__device__ int   g_csr[EE];                // src ids sorted by dst
__device__ float g_x[(size_t)NN * HD];     // x = (feat*nsrc)@W1 ; later agg2*ndst
__device__ float g_y[(size_t)NN * HD];     // y = relu(agg1*ndst+b1)*nsrc

// ---------------------------------------------------------------------------
// Degrees (int counts)
// ---------------------------------------------------------------------------
__global__ void deg_kernel(const int* __restrict__ src, const int* __restrict__ dst, int E) {
    int i = blockIdx.x * blockDim.x + threadIdx.x;
    if (i < E) {
        atomicAdd(&g_cnt_out[src[i]], 1);
        atomicAdd(&g_cnt_in[dst[i]], 1);
    }
}

__global__ void norm_kernel(int N) {
    int i = blockIdx.x * blockDim.x + threadIdx.x;
    if (i < N) {
        g_nsrc[i] = rsqrtf(fmaxf((float)g_cnt_out[i], 1.0f));
        g_ndst[i] = rsqrtf(fmaxf((float)g_cnt_in[i], 1.0f));
    }
}

// ---------------------------------------------------------------------------
// 3-kernel exclusive scan of g_cnt_in -> g_off, also init g_cursor
// ---------------------------------------------------------------------------
__global__ void scan_part(int N) {
    __shared__ int sh[SCAN_B];
    int i = blockIdx.x * SCAN_B + threadIdx.x;
    int v = (i < N) ? g_cnt_in[i] : 0;
    sh[threadIdx.x] = v;
    __syncthreads();
    for (int off = SCAN_B / 2; off > 0; off >>= 1) {
        if (threadIdx.x < off) sh[threadIdx.x] += sh[threadIdx.x + off];
        __syncthreads();
    }
    if (threadIdx.x == 0) g_bsum[blockIdx.x] = sh[0];
}

__global__ void scan_mid(int nb) {
    __shared__ int sh[512];
    int t = threadIdx.x;
    int v = (t < nb) ? g_bsum[t] : 0;
    sh[t] = v;
    __syncthreads();
    for (int off = 1; off < 512; off <<= 1) {
        int add = (t >= off) ? sh[t - off] : 0;
        __syncthreads();
        sh[t] += add;
        __syncthreads();
    }
    if (t < nb) g_bsum[t] = sh[t] - v;   // exclusive
}

__global__ void scan_final(int N, int E) {
    __shared__ int sh[SCAN_B];
    int i = blockIdx.x * SCAN_B + threadIdx.x;
    int t = threadIdx.x;
    int v = (i < N) ? g_cnt_in[i] : 0;
    sh[t] = v;
    __syncthreads();
    for (int off = 1; off < SCAN_B; off <<= 1) {
        int add = (t >= off) ? sh[t - off] : 0;
        __syncthreads();
        sh[t] += add;
        __syncthreads();
    }
    int excl = sh[t] - v + g_bsum[blockIdx.x];
    if (i < N) {
        g_off[i] = excl;
        g_cursor[i] = excl;
        if (i == N - 1) g_off[N] = E;
    }
}

// ---------------------------------------------------------------------------
// Fill CSR: for each edge, place src into dst's segment
// ---------------------------------------------------------------------------
__global__ void fill_kernel(const int* __restrict__ src, const int* __restrict__ dst, int E) {
    int i = blockIdx.x * blockDim.x + threadIdx.x;
    if (i < E) {
        int p = atomicAdd(&g_cursor[dst[i]], 1);
        g_csr[p] = src[i];
    }
}

// ---------------------------------------------------------------------------
// GEMM1: x = (feat * nsrc) @ W1    [N,128] x [128,64]
// ---------------------------------------------------------------------------
__global__ void __launch_bounds__(256) gemm1_kernel(const float* __restrict__ feat,
                                                    const float* __restrict__ W1, int N) {
    __shared__ float As[64][68];
    __shared__ float Ws[64][64];
    int tx = threadIdx.x & 15, ty = threadIdx.x >> 4;
    int r0 = blockIdx.x * 64;

    float acc[4][4] = {};

    for (int k0 = 0; k0 < FD; k0 += 64) {
        for (int idx = threadIdx.x; idx < 1024; idx += 256) {
            int r = idx >> 4;
            int c4 = idx & 15;
            int row = r0 + r;
            float4 v = make_float4(0.f, 0.f, 0.f, 0.f);
            float s = 0.f;
            if (row < N) {
                v = *(const float4*)(feat + (size_t)row * FD + k0 + c4 * 4);
                s = g_nsrc[row];
            }
            v.x *= s; v.y *= s; v.z *= s; v.w *= s;
            *(float4*)&As[r][c4 * 4] = v;
        }
        for (int idx = threadIdx.x; idx < 1024; idx += 256) {
            ((float4*)Ws)[idx] = ((const float4*)(W1 + (size_t)k0 * HD))[idx];
        }
        __syncthreads();

#pragma unroll
        for (int k = 0; k < 64; k++) {
            float a0 = As[ty * 4 + 0][k];
            float a1 = As[ty * 4 + 1][k];
            float a2 = As[ty * 4 + 2][k];
            float a3 = As[ty * 4 + 3][k];
            float4 w = *(float4*)&Ws[k][tx * 4];
            acc[0][0] += a0 * w.x; acc[0][1] += a0 * w.y; acc[0][2] += a0 * w.z; acc[0][3] += a0 * w.w;
            acc[1][0] += a1 * w.x; acc[1][1] += a1 * w.y; acc[1][2] += a1 * w.z; acc[1][3] += a1 * w.w;
            acc[2][0] += a2 * w.x; acc[2][1] += a2 * w.y; acc[2][2] += a2 * w.z; acc[2][3] += a2 * w.w;
            acc[3][0] += a3 * w.x; acc[3][1] += a3 * w.y; acc[3][2] += a3 * w.z; acc[3][3] += a3 * w.w;
        }
        __syncthreads();
    }

#pragma unroll
    for (int i = 0; i < 4; i++) {
        int row = r0 + ty * 4 + i;
        if (row < N) {
            float4 o = make_float4(acc[i][0], acc[i][1], acc[i][2], acc[i][3]);
            *(float4*)(g_x + (size_t)row * HD + tx * 4) = o;
        }
    }
}

// ---------------------------------------------------------------------------
// Gather 1: y[n] = relu( (sum_{s in in(n)} x[s]) * ndst[n] + b1 ) * nsrc[n]
// One warp per node; each lane owns 2 features (float2).
// ---------------------------------------------------------------------------
__global__ void __launch_bounds__(256) gather1_kernel(const float* __restrict__ b1, int N) {
    int warp = (blockIdx.x * blockDim.x + threadIdx.x) >> 5;
    int lane = threadIdx.x & 31;
    if (warp >= N) return;
    int beg = g_off[warp], end = g_off[warp + 1];

    float ax = 0.f, ay = 0.f;
    int j = beg;
    for (; j + 4 <= end; j += 4) {
        int s0 = g_csr[j], s1 = g_csr[j + 1], s2 = g_csr[j + 2], s3 = g_csr[j + 3];
        float2 v0 = *(const float2*)(g_x + (size_t)s0 * HD + lane * 2);
        float2 v1 = *(const float2*)(g_x + (size_t)s1 * HD + lane * 2);
        float2 v2 = *(const float2*)(g_x + (size_t)s2 * HD + lane * 2);
        float2 v3 = *(const float2*)(g_x + (size_t)s3 * HD + lane * 2);
        ax += (v0.x + v1.x) + (v2.x + v3.x);
        ay += (v0.y + v1.y) + (v2.y + v3.y);
    }
    for (; j < end; j++) {
        int s = g_csr[j];
        float2 v = *(const float2*)(g_x + (size_t)s * HD + lane * 2);
        ax += v.x; ay += v.y;
    }

    float nd = g_ndst[warp];
    float ns = g_nsrc[warp];
    float2 b = *(const float2*)(b1 + lane * 2);
    float2 o;
    o.x = fmaxf(ax * nd + b.x, 0.f) * ns;
    o.y = fmaxf(ay * nd + b.y, 0.f) * ns;
    *(float2*)(g_y + (size_t)warp * HD + lane * 2) = o;
}

// ---------------------------------------------------------------------------
// Gather 2: g_x[n] = (sum_{s in in(n)} y[s]) * ndst[n]   (ndst folded in;
// row scaling commutes through the feature-dim GEMM)
// ---------------------------------------------------------------------------
__global__ void __launch_bounds__(256) gather2_kernel(int N) {
    int warp = (blockIdx.x * blockDim.x + threadIdx.x) >> 5;
    int lane = threadIdx.x & 31;
    if (warp >= N) return;
    int beg = g_off[warp], end = g_off[warp + 1];

    float ax = 0.f, ay = 0.f;
    int j = beg;
    for (; j + 4 <= end; j += 4) {
        int s0 = g_csr[j], s1 = g_csr[j + 1], s2 = g_csr[j + 2], s3 = g_csr[j + 3];
        float2 v0 = *(const float2*)(g_y + (size_t)s0 * HD + lane * 2);
        float2 v1 = *(const float2*)(g_y + (size_t)s1 * HD + lane * 2);
        float2 v2 = *(const float2*)(g_y + (size_t)s2 * HD + lane * 2);
        float2 v3 = *(const float2*)(g_y + (size_t)s3 * HD + lane * 2);
        ax += (v0.x + v1.x) + (v2.x + v3.x);
        ay += (v0.y + v1.y) + (v2.y + v3.y);
    }
    for (; j < end; j++) {
        int s = g_csr[j];
        float2 v = *(const float2*)(g_y + (size_t)s * HD + lane * 2);
        ax += v.x; ay += v.y;
    }

    float nd = g_ndst[warp];
    float2 o = make_float2(ax * nd, ay * nd);
    *(float2*)(g_x + (size_t)warp * HD + lane * 2) = o;
}

// ---------------------------------------------------------------------------
// Final: z = (a@W_mu + b_mu) + noise * exp(a@W_sig + b_sig), a = g_x (=agg2*ndst)
// ---------------------------------------------------------------------------
__global__ void __launch_bounds__(256) final_kernel(const float* __restrict__ noise,
                                                    const float* __restrict__ W_mu,
                                                    const float* __restrict__ b_mu,
                                                    const float* __restrict__ W_sig,
                                                    const float* __restrict__ b_sig,
                                                    float* __restrict__ out, int N) {
    __shared__ float As[64][36];
    __shared__ float Wc[32][128];
    int tx = threadIdx.x & 15, ty = threadIdx.x >> 4;
    int r0 = blockIdx.x * 64;

    float am[4][4] = {};
    float asg[4][4] = {};

    for (int k0 = 0; k0 < HD; k0 += 32) {
        for (int idx = threadIdx.x; idx < 512; idx += 256) {
            int r = idx >> 3;
            int c4 = idx & 7;
            int row = r0 + r;
            float4 v = make_float4(0.f, 0.f, 0.f, 0.f);
            if (row < N) v = *(const float4*)(g_x + (size_t)row * HD + k0 + c4 * 4);
            *(float4*)&As[r][c4 * 4] = v;
        }
        for (int idx = threadIdx.x; idx < 1024; idx += 256) {
            int k = idx >> 5;
            int c4 = idx & 31;
            if (c4 < 16) {
                *(float4*)&Wc[k][c4 * 4] = *(const float4*)(W_mu + (size_t)(k0 + k) * HD + c4 * 4);
            } else {
                *(float4*)&Wc[k][64 + (c4 - 16) * 4] =
                    *(const float4*)(W_sig + (size_t)(k0 + k) * HD + (c4 - 16) * 4);
            }
        }
        __syncthreads();

#pragma unroll
        for (int k = 0; k < 32; k++) {
            float a0 = As[ty * 4 + 0][k];
            float a1 = As[ty * 4 + 1][k];
            float a2 = As[ty * 4 + 2][k];
            float a3 = As[ty * 4 + 3][k];
            float4 wm = *(float4*)&Wc[k][tx * 4];
            float4 ws = *(float4*)&Wc[k][64 + tx * 4];
            am[0][0] += a0 * wm.x; am[0][1] += a0 * wm.y; am[0][2] += a0 * wm.z; am[0][3] += a0 * wm.w;
            am[1][0] += a1 * wm.x; am[1][1] += a1 * wm.y; am[1][2] += a1 * wm.z; am[1][3] += a1 * wm.w;
            am[2][0] += a2 * wm.x; am[2][1] += a2 * wm.y; am[2][2] += a2 * wm.z; am[2][3] += a2 * wm.w;
            am[3][0] += a3 * wm.x; am[3][1] += a3 * wm.y; am[3][2] += a3 * wm.z; am[3][3] += a3 * wm.w;
            asg[0][0] += a0 * ws.x; asg[0][1] += a0 * ws.y; asg[0][2] += a0 * ws.z; asg[0][3] += a0 * ws.w;
            asg[1][0] += a1 * ws.x; asg[1][1] += a1 * ws.y; asg[1][2] += a1 * ws.z; asg[1][3] += a1 * ws.w;
            asg[2][0] += a2 * ws.x; asg[2][1] += a2 * ws.y; asg[2][2] += a2 * ws.z; asg[2][3] += a2 * ws.w;
            asg[3][0] += a3 * ws.x; asg[3][1] += a3 * ws.y; asg[3][2] += a3 * ws.z; asg[3][3] += a3 * ws.w;
        }
        __syncthreads();
    }

    float4 bm = *(const float4*)(b_mu + tx * 4);
    float4 bs = *(const float4*)(b_sig + tx * 4);

#pragma unroll
    for (int i = 0; i < 4; i++) {
        int row = r0 + ty * 4 + i;
        if (row < N) {
            float4 nz = *(const float4*)(noise + (size_t)row * HD + tx * 4);
            float4 o;
            o.x = (am[i][0] + bm.x) + nz.x * expf(asg[i][0] + bs.x);
            o.y = (am[i][1] + bm.y) + nz.y * expf(asg[i][1] + bs.y);
            o.z = (am[i][2] + bm.z) + nz.z * expf(asg[i][2] + bs.z);
            o.w = (am[i][3] + bm.w) + nz.w * expf(asg[i][3] + bs.w);
            *(float4*)(out + (size_t)row * HD + tx * 4) = o;
        }
    }
}

// ---------------------------------------------------------------------------
// Launch
// ---------------------------------------------------------------------------
extern "C" void kernel_launch(void* const* d_in, const int* in_sizes, int n_in,
                              void* d_out, int out_size) {
    const float* feat  = (const float*)d_in[0];
    const int*   src   = (const int*)d_in[1];
    const int*   dst   = (const int*)d_in[2];
    const float* noise = (const float*)d_in[3];
    const float* W1    = (const float*)d_in[4];
    const float* b1    = (const float*)d_in[5];
    const float* W_mu  = (const float*)d_in[6];
    const float* b_mu  = (const float*)d_in[7];
    const float* W_sig = (const float*)d_in[8];
    const float* b_sig = (const float*)d_in[9];

    int N = in_sizes[0] / FD;
    int E = in_sizes[1];

    void *p_cnt_out, *p_cnt_in;
    cudaGetSymbolAddress(&p_cnt_out, g_cnt_out);
    cudaGetSymbolAddress(&p_cnt_in,  g_cnt_in);
    cudaMemsetAsync(p_cnt_out, 0, sizeof(int) * NN);
    cudaMemsetAsync(p_cnt_in,  0, sizeof(int) * NN);

    deg_kernel<<<(E + 255) / 256, 256>>>(src, dst, E);
    norm_kernel<<<(N + 255) / 256, 256>>>(N);

    int nb = (N + SCAN_B - 1) / SCAN_B;
    scan_part<<<nb, SCAN_B>>>(N);
    scan_mid<<<1, 512>>>(nb);
    scan_final<<<nb, SCAN_B>>>(N, E);
    fill_kernel<<<(E + 255) / 256, 256>>>(src, dst, E);

    gemm1_kernel<<<(N + 63) / 64, 256>>>(feat, W1, N);

    int gblocks = (N * 32 + 255) / 256;
    gather1_kernel<<<gblocks, 256>>>(b1, N);
    gather2_kernel<<<gblocks, 256>>>(N);

    final_kernel<<<(N + 63) / 64, 256>>>(noise, W_mu, b_mu, W_sig, b_sig,
                                         (float*)d_out, N);
}

// round 3
// speedup vs baseline: 1.4877x; 1.0272x over previous
#include <cuda_runtime.h>
#include <cuda_fp16.h>
#include <math.h>

#define NN 100000
#define EE 1600000
#define FD 128
#define HD 64
#define SCAN_B 256

// Scratch (device globals)
__device__ int    g_cnt_out[NN];
__device__ int    g_cnt_in[NN];
__device__ float  g_nsrc[NN];
__device__ float  g_ndst[NN];
__device__ int    g_bsum[512];
__device__ int    g_off[NN + 1];
__device__ int    g_cursor[NN];
__device__ int    g_csr[EE];
__device__ __half g_x16[(size_t)NN * HD];   // x = (feat*nsrc)@W1 (fp16)
__device__ __half g_y16[(size_t)NN * HD];   // y = relu(agg1*ndst+b1)*nsrc (fp16)
__device__ float  g_a2[(size_t)NN * HD];    // agg2*ndst (fp32, GEMM input)

// ---------------------------------------------------------------------------
// Degrees (int counts), 4 edges per thread
// ---------------------------------------------------------------------------
__global__ void deg_kernel(const int* __restrict__ src, const int* __restrict__ dst, int E) {
    int i = (blockIdx.x * blockDim.x + threadIdx.x) * 4;
    if (i + 4 <= E) {
        int4 s = *(const int4*)(src + i);
        int4 d = *(const int4*)(dst + i);
        atomicAdd(&g_cnt_out[s.x], 1); atomicAdd(&g_cnt_out[s.y], 1);
        atomicAdd(&g_cnt_out[s.z], 1); atomicAdd(&g_cnt_out[s.w], 1);
        atomicAdd(&g_cnt_in[d.x], 1);  atomicAdd(&g_cnt_in[d.y], 1);
        atomicAdd(&g_cnt_in[d.z], 1);  atomicAdd(&g_cnt_in[d.w], 1);
    } else {
        for (int j = i; j < E; j++) {
            atomicAdd(&g_cnt_out[src[j]], 1);
            atomicAdd(&g_cnt_in[dst[j]], 1);
        }
    }
}

__global__ void norm_kernel(int N) {
    int i = blockIdx.x * blockDim.x + threadIdx.x;
    if (i < N) {
        g_nsrc[i] = rsqrtf(fmaxf((float)g_cnt_out[i], 1.0f));
        g_ndst[i] = rsqrtf(fmaxf((float)g_cnt_in[i], 1.0f));
    }
}

// ---------------------------------------------------------------------------
// 3-kernel exclusive scan of g_cnt_in -> g_off (+ cursor init)
// ---------------------------------------------------------------------------
__global__ void scan_part(int N) {
    __shared__ int sh[SCAN_B];
    int i = blockIdx.x * SCAN_B + threadIdx.x;
    int v = (i < N) ? g_cnt_in[i] : 0;
    sh[threadIdx.x] = v;
    __syncthreads();
    for (int off = SCAN_B / 2; off > 0; off >>= 1) {
        if (threadIdx.x < off) sh[threadIdx.x] += sh[threadIdx.x + off];
        __syncthreads();
    }
    if (threadIdx.x == 0) g_bsum[blockIdx.x] = sh[0];
}

__global__ void scan_mid(int nb) {
    __shared__ int wsum[16];
    int t = threadIdx.x;                 // 512 threads
    int v = (t < nb) ? g_bsum[t] : 0;
    int x = v;
#pragma unroll
    for (int o = 1; o < 32; o <<= 1) {
        int n = __shfl_up_sync(0xffffffffu, x, o);
        if ((t & 31) >= o) x += n;
    }
    if ((t & 31) == 31) wsum[t >> 5] = x;
    __syncthreads();
    if (t < 16) {
        int w = wsum[t];
#pragma unroll
        for (int o = 1; o < 16; o <<= 1) {
            int n = __shfl_up_sync(0xffffu, w, o);
            if (t >= o) w += n;
        }
        wsum[t] = w;
    }
    __syncthreads();
    int pre = (t >= 32) ? wsum[(t >> 5) - 1] : 0;
    if (t < nb) g_bsum[t] = x + pre - v;    // exclusive
}

__global__ void scan_final(int N, int E) {
    __shared__ int sh[SCAN_B];
    int i = blockIdx.x * SCAN_B + threadIdx.x;
    int t = threadIdx.x;
    int v = (i < N) ? g_cnt_in[i] : 0;
    sh[t] = v;
    __syncthreads();
    for (int off = 1; off < SCAN_B; off <<= 1) {
        int add = (t >= off) ? sh[t - off] : 0;
        __syncthreads();
        sh[t] += add;
        __syncthreads();
    }
    int excl = sh[t] - v + g_bsum[blockIdx.x];
    if (i < N) {
        g_off[i] = excl;
        g_cursor[i] = excl;
        if (i == N - 1) g_off[N] = E;
    }
}

__global__ void fill_kernel(const int* __restrict__ src, const int* __restrict__ dst, int E) {
    int i = blockIdx.x * blockDim.x + threadIdx.x;
    if (i < E) {
        int p = atomicAdd(&g_cursor[dst[i]], 1);
        g_csr[p] = src[i];
    }
}

// ---------------------------------------------------------------------------
// GEMM1: x = (feat * nsrc) @ W1    [N,128] x [128,64], fp16 output
// ---------------------------------------------------------------------------
__global__ void __launch_bounds__(256) gemm1_kernel(const float* __restrict__ feat,
                                                    const float* __restrict__ W1, int N) {
    __shared__ float As[64][68];
    __shared__ float Ws[64][64];
    int tx = threadIdx.x & 15, ty = threadIdx.x >> 4;
    int r0 = blockIdx.x * 64;

    float acc[4][4] = {};

    for (int k0 = 0; k0 < FD; k0 += 64) {
        for (int idx = threadIdx.x; idx < 1024; idx += 256) {
            int r = idx >> 4;
            int c4 = idx & 15;
            int row = r0 + r;
            float4 v = make_float4(0.f, 0.f, 0.f, 0.f);
            float s = 0.f;
            if (row < N) {
                v = *(const float4*)(feat + (size_t)row * FD + k0 + c4 * 4);
                s = g_nsrc[row];
            }
            v.x *= s; v.y *= s; v.z *= s; v.w *= s;
            *(float4*)&As[r][c4 * 4] = v;
        }
        for (int idx = threadIdx.x; idx < 1024; idx += 256) {
            ((float4*)Ws)[idx] = ((const float4*)(W1 + (size_t)k0 * HD))[idx];
        }
        __syncthreads();

#pragma unroll
        for (int k = 0; k < 64; k++) {
            float a0 = As[ty * 4 + 0][k];
            float a1 = As[ty * 4 + 1][k];
            float a2 = As[ty * 4 + 2][k];
            float a3 = As[ty * 4 + 3][k];
            float4 w = *(float4*)&Ws[k][tx * 4];
            acc[0][0] += a0 * w.x; acc[0][1] += a0 * w.y; acc[0][2] += a0 * w.z; acc[0][3] += a0 * w.w;
            acc[1][0] += a1 * w.x; acc[1][1] += a1 * w.y; acc[1][2] += a1 * w.z; acc[1][3] += a1 * w.w;
            acc[2][0] += a2 * w.x; acc[2][1] += a2 * w.y; acc[2][2] += a2 * w.z; acc[2][3] += a2 * w.w;
            acc[3][0] += a3 * w.x; acc[3][1] += a3 * w.y; acc[3][2] += a3 * w.z; acc[3][3] += a3 * w.w;
        }
        __syncthreads();
    }

#pragma unroll
    for (int i = 0; i < 4; i++) {
        int row = r0 + ty * 4 + i;
        if (row < N) {
            __half2 h0 = __floats2half2_rn(acc[i][0], acc[i][1]);
            __half2 h1 = __floats2half2_rn(acc[i][2], acc[i][3]);
            uint2 pk;
            pk.x = *(unsigned*)&h0;
            pk.y = *(unsigned*)&h1;
            *(uint2*)(g_x16 + (size_t)row * HD + tx * 4) = pk;
        }
    }
}

// ---------------------------------------------------------------------------
// Gather 1: y16[n] = fp16( relu(sum x16[s] * ndst + b1) * nsrc )
// One warp per node; lane owns 2 features (one half2 = 4B).
// ---------------------------------------------------------------------------
__global__ void __launch_bounds__(256) gather1_kernel(const float* __restrict__ b1, int N) {
    int warp = (blockIdx.x * blockDim.x + threadIdx.x) >> 5;
    int lane = threadIdx.x & 31;
    if (warp >= N) return;
    int beg = g_off[warp], end = g_off[warp + 1];

    float ax = 0.f, ay = 0.f;
    int j = beg;
    for (; j + 4 <= end; j += 4) {
        int s0 = g_csr[j], s1 = g_csr[j + 1], s2 = g_csr[j + 2], s3 = g_csr[j + 3];
        float2 v0 = __half22float2(*(const __half2*)(g_x16 + (size_t)s0 * HD + lane * 2));
        float2 v1 = __half22float2(*(const __half2*)(g_x16 + (size_t)s1 * HD + lane * 2));
        float2 v2 = __half22float2(*(const __half2*)(g_x16 + (size_t)s2 * HD + lane * 2));
        float2 v3 = __half22float2(*(const __half2*)(g_x16 + (size_t)s3 * HD + lane * 2));
        ax += (v0.x + v1.x) + (v2.x + v3.x);
        ay += (v0.y + v1.y) + (v2.y + v3.y);
    }
    for (; j < end; j++) {
        int s = g_csr[j];
        float2 v = __half22float2(*(const __half2*)(g_x16 + (size_t)s * HD + lane * 2));
        ax += v.x; ay += v.y;
    }

    float nd = g_ndst[warp];
    float ns = g_nsrc[warp];
    float2 b = *(const float2*)(b1 + lane * 2);
    float ox = fmaxf(ax * nd + b.x, 0.f) * ns;
    float oy = fmaxf(ay * nd + b.y, 0.f) * ns;
    *(__half2*)(g_y16 + (size_t)warp * HD + lane * 2) = __floats2half2_rn(ox, oy);
}

// ---------------------------------------------------------------------------
// Gather 2: a2[n] = (sum y16[s]) * ndst[n]   (fp32 out)
// ---------------------------------------------------------------------------
__global__ void __launch_bounds__(256) gather2_kernel(int N) {
    int warp = (blockIdx.x * blockDim.x + threadIdx.x) >> 5;
    int lane = threadIdx.x & 31;
    if (warp >= N) return;
    int beg = g_off[warp], end = g_off[warp + 1];

    float ax = 0.f, ay = 0.f;
    int j = beg;
    for (; j + 4 <= end; j += 4) {
        int s0 = g_csr[j], s1 = g_csr[j + 1], s2 = g_csr[j + 2], s3 = g_csr[j + 3];
        float2 v0 = __half22float2(*(const __half2*)(g_y16 + (size_t)s0 * HD + lane * 2));
        float2 v1 = __half22float2(*(const __half2*)(g_y16 + (size_t)s1 * HD + lane * 2));
        float2 v2 = __half22float2(*(const __half2*)(g_y16 + (size_t)s2 * HD + lane * 2));
        float2 v3 = __half22float2(*(const __half2*)(g_y16 + (size_t)s3 * HD + lane * 2));
        ax += (v0.x + v1.x) + (v2.x + v3.x);
        ay += (v0.y + v1.y) + (v2.y + v3.y);
    }
    for (; j < end; j++) {
        int s = g_csr[j];
        float2 v = __half22float2(*(const __half2*)(g_y16 + (size_t)s * HD + lane * 2));
        ax += v.x; ay += v.y;
    }

    float nd = g_ndst[warp];
    *(float2*)(g_a2 + (size_t)warp * HD + lane * 2) = make_float2(ax * nd, ay * nd);
}

// ---------------------------------------------------------------------------
// Final: z = (a@W_mu + b_mu) + noise * exp(a@W_sig + b_sig), a = g_a2
// ---------------------------------------------------------------------------
__global__ void __launch_bounds__(256) final_kernel(const float* __restrict__ noise,
                                                    const float* __restrict__ W_mu,
                                                    const float* __restrict__ b_mu,
                                                    const float* __restrict__ W_sig,
                                                    const float* __restrict__ b_sig,
                                                    float* __restrict__ out, int N) {
    __shared__ float As[64][36];
    __shared__ float Wc[32][128];
    int tx = threadIdx.x & 15, ty = threadIdx.x >> 4;
    int r0 = blockIdx.x * 64;

    float am[4][4] = {};
    float asg[4][4] = {};

    for (int k0 = 0; k0 < HD; k0 += 32) {
        for (int idx = threadIdx.x; idx < 512; idx += 256) {
            int r = idx >> 3;
            int c4 = idx & 7;
            int row = r0 + r;
            float4 v = make_float4(0.f, 0.f, 0.f, 0.f);
            if (row < N) v = *(const float4*)(g_a2 + (size_t)row * HD + k0 + c4 * 4);
            *(float4*)&As[r][c4 * 4] = v;
        }
        for (int idx = threadIdx.x; idx < 1024; idx += 256) {
            int k = idx >> 5;
            int c4 = idx & 31;
            if (c4 < 16) {
                *(float4*)&Wc[k][c4 * 4] = *(const float4*)(W_mu + (size_t)(k0 + k) * HD + c4 * 4);
            } else {
                *(float4*)&Wc[k][64 + (c4 - 16) * 4] =
                    *(const float4*)(W_sig + (size_t)(k0 + k) * HD + (c4 - 16) * 4);
            }
        }
        __syncthreads();

#pragma unroll
        for (int k = 0; k < 32; k++) {
            float a0 = As[ty * 4 + 0][k];
            float a1 = As[ty * 4 + 1][k];
            float a2 = As[ty * 4 + 2][k];
            float a3 = As[ty * 4 + 3][k];
            float4 wm = *(float4*)&Wc[k][tx * 4];
            float4 ws = *(float4*)&Wc[k][64 + tx * 4];
            am[0][0] += a0 * wm.x; am[0][1] += a0 * wm.y; am[0][2] += a0 * wm.z; am[0][3] += a0 * wm.w;
            am[1][0] += a1 * wm.x; am[1][1] += a1 * wm.y; am[1][2] += a1 * wm.z; am[1][3] += a1 * wm.w;
            am[2][0] += a2 * wm.x; am[2][1] += a2 * wm.y; am[2][2] += a2 * wm.z; am[2][3] += a2 * wm.w;
            am[3][0] += a3 * wm.x; am[3][1] += a3 * wm.y; am[3][2] += a3 * wm.z; am[3][3] += a3 * wm.w;
            asg[0][0] += a0 * ws.x; asg[0][1] += a0 * ws.y; asg[0][2] += a0 * ws.z; asg[0][3] += a0 * ws.w;
            asg[1][0] += a1 * ws.x; asg[1][1] += a1 * ws.y; asg[1][2] += a1 * ws.z; asg[1][3] += a1 * ws.w;
            asg[2][0] += a2 * ws.x; asg[2][1] += a2 * ws.y; asg[2][2] += a2 * ws.z; asg[2][3] += a2 * ws.w;
            asg[3][0] += a3 * ws.x; asg[3][1] += a3 * ws.y; asg[3][2] += a3 * ws.z; asg[3][3] += a3 * ws.w;
        }
        __syncthreads();
    }

    float4 bm = *(const float4*)(b_mu + tx * 4);
    float4 bs = *(const float4*)(b_sig + tx * 4);

#pragma unroll
    for (int i = 0; i < 4; i++) {
        int row = r0 + ty * 4 + i;
        if (row < N) {
            float4 nz = *(const float4*)(noise + (size_t)row * HD + tx * 4);
            float4 o;
            o.x = (am[i][0] + bm.x) + nz.x * expf(asg[i][0] + bs.x);
            o.y = (am[i][1] + bm.y) + nz.y * expf(asg[i][1] + bs.y);
            o.z = (am[i][2] + bm.z) + nz.z * expf(asg[i][2] + bs.z);
            o.w = (am[i][3] + bm.w) + nz.w * expf(asg[i][3] + bs.w);
            *(float4*)(out + (size_t)row * HD + tx * 4) = o;
        }
    }
}

// ---------------------------------------------------------------------------
// Launch (second stream created once, before any graph capture)
// ---------------------------------------------------------------------------
static cudaStream_t s_gemm = nullptr;
static cudaEvent_t  s_evNorm = nullptr, s_evGemm = nullptr;

extern "C" void kernel_launch(void* const* d_in, const int* in_sizes, int n_in,
                              void* d_out, int out_size) {
    const float* feat  = (const float*)d_in[0];
    const int*   src   = (const int*)d_in[1];
    const int*   dst   = (const int*)d_in[2];
    const float* noise = (const float*)d_in[3];
    const float* W1    = (const float*)d_in[4];
    const float* b1    = (const float*)d_in[5];
    const float* W_mu  = (const float*)d_in[6];
    const float* b_mu  = (const float*)d_in[7];
    const float* W_sig = (const float*)d_in[8];
    const float* b_sig = (const float*)d_in[9];

    int N = in_sizes[0] / FD;
    int E = in_sizes[1];

    if (s_gemm == nullptr) {
        cudaStreamCreateWithFlags(&s_gemm, cudaStreamNonBlocking);
        cudaEventCreateWithFlags(&s_evNorm, cudaEventDisableTiming);
        cudaEventCreateWithFlags(&s_evGemm, cudaEventDisableTiming);
    }

    void *p_cnt_out, *p_cnt_in;
    cudaGetSymbolAddress(&p_cnt_out, g_cnt_out);
    cudaGetSymbolAddress(&p_cnt_in,  g_cnt_in);
    cudaMemsetAsync(p_cnt_out, 0, sizeof(int) * NN);
    cudaMemsetAsync(p_cnt_in,  0, sizeof(int) * NN);

    deg_kernel<<<(E / 4 + 255) / 256, 256>>>(src, dst, E);
    norm_kernel<<<(N + 255) / 256, 256>>>(N);

    // Fork: gemm1 depends only on norm; CSR build proceeds on main stream.
    cudaEventRecord(s_evNorm, 0);
    cudaStreamWaitEvent(s_gemm, s_evNorm, 0);
    gemm1_kernel<<<(N + 63) / 64, 256, 0, s_gemm>>>(feat, W1, N);
    cudaEventRecord(s_evGemm, s_gemm);

    int nb = (N + SCAN_B - 1) / SCAN_B;
    scan_part<<<nb, SCAN_B>>>(N);
    scan_mid<<<1, 512>>>(nb);
    scan_final<<<nb, SCAN_B>>>(N, E);
    fill_kernel<<<(E + 255) / 256, 256>>>(src, dst, E);

    // Join before gather1 (needs both CSR and x16)
    cudaStreamWaitEvent(0, s_evGemm, 0);

    int gblocks = (N * 32 + 255) / 256;
    gather1_kernel<<<gblocks, 256>>>(b1, N);
    gather2_kernel<<<gblocks, 256>>>(N);

    final_kernel<<<(N + 63) / 64, 256>>>(noise, W_mu, b_mu, W_sig, b_sig,
                                         (float*)d_out, N);
}

// round 4
// speedup vs baseline: 1.5926x; 1.0705x over previous
#include <cuda_runtime.h>
#include <cuda_fp16.h>
#include <math.h>

#define NN 100000
#define EE 1600000
#define FD 128
#define HD 64

// Scratch (device globals)
__device__ int    g_cnt[2 * NN + 32];       // [0..NN)=out, [NN..2NN)=in, [2NN]=scan ticket
__device__ float  g_nsrc[NN];
__device__ float  g_ndst[NN];
__device__ int    g_off[NN];                // segment begin per node (unordered layout)
__device__ int    g_cursor[NN];
__device__ int    g_csr[EE];
__device__ __half g_x16[(size_t)NN * HD];
__device__ __half g_y16[(size_t)NN * HD];
__device__ float  g_a2[(size_t)NN * HD];

// ---------------------------------------------------------------------------
// Degrees
// ---------------------------------------------------------------------------
__global__ void deg_kernel(const int* __restrict__ src, const int* __restrict__ dst, int E) {
    int i = (blockIdx.x * blockDim.x + threadIdx.x) * 4;
    if (i + 4 <= E) {
        int4 s = *(const int4*)(src + i);
        int4 d = *(const int4*)(dst + i);
        atomicAdd(&g_cnt[s.x], 1); atomicAdd(&g_cnt[s.y], 1);
        atomicAdd(&g_cnt[s.z], 1); atomicAdd(&g_cnt[s.w], 1);
        atomicAdd(&g_cnt[NN + d.x], 1); atomicAdd(&g_cnt[NN + d.y], 1);
        atomicAdd(&g_cnt[NN + d.z], 1); atomicAdd(&g_cnt[NN + d.w], 1);
    } else {
        for (int j = i; j < E; j++) {
            atomicAdd(&g_cnt[src[j]], 1);
            atomicAdd(&g_cnt[NN + dst[j]], 1);
        }
    }
}

// ---------------------------------------------------------------------------
// Scan + norm fused. Node segments need only be DISJOINT, not ordered, so each
// block grabs its base offset from an atomic ticket.
// ---------------------------------------------------------------------------
__global__ void __launch_bounds__(256) scan_norm_kernel(int N) {
    __shared__ int wsum[8];
    __shared__ int sbase;
    int i = blockIdx.x * 256 + threadIdx.x;
    int lane = threadIdx.x & 31, wid = threadIdx.x >> 5;

    int cin = (i < N) ? g_cnt[NN + i] : 0;
    int x = cin;
#pragma unroll
    for (int o = 1; o < 32; o <<= 1) {
        int n = __shfl_up_sync(0xffffffffu, x, o);
        if (lane >= o) x += n;
    }
    if (lane == 31) wsum[wid] = x;
    __syncthreads();
    if (threadIdx.x == 0) {
        int run = 0;
#pragma unroll
        for (int w = 0; w < 8; w++) { run += wsum[w]; wsum[w] = run; }  // inclusive
        sbase = atomicAdd(&g_cnt[2 * NN], run);
    }
    __syncthreads();
    int excl = x - cin + (wid > 0 ? wsum[wid - 1] : 0) + sbase;
    if (i < N) {
        g_off[i] = excl;
        g_cursor[i] = excl;
        g_nsrc[i] = rsqrtf(fmaxf((float)g_cnt[i], 1.0f));
        g_ndst[i] = rsqrtf(fmaxf((float)cin, 1.0f));
    }
}

__global__ void fill_kernel(const int* __restrict__ src, const int* __restrict__ dst, int E) {
    int i = blockIdx.x * blockDim.x + threadIdx.x;
    if (i < E) {
        int p = atomicAdd(&g_cursor[dst[i]], 1);
        g_csr[p] = src[i];
    }
}

// ---------------------------------------------------------------------------
// GEMM1: x16 = fp16( (feat * nsrc) @ W1 )
// ---------------------------------------------------------------------------
__global__ void __launch_bounds__(256) gemm1_kernel(const float* __restrict__ feat,
                                                    const float* __restrict__ W1, int N) {
    __shared__ float As[64][68];
    __shared__ float Ws[64][64];
    int tx = threadIdx.x & 15, ty = threadIdx.x >> 4;
    int r0 = blockIdx.x * 64;

    float acc[4][4] = {};

    for (int k0 = 0; k0 < FD; k0 += 64) {
        for (int idx = threadIdx.x; idx < 1024; idx += 256) {
            int r = idx >> 4;
            int c4 = idx & 15;
            int row = r0 + r;
            float4 v = make_float4(0.f, 0.f, 0.f, 0.f);
            float s = 0.f;
            if (row < N) {
                v = *(const float4*)(feat + (size_t)row * FD + k0 + c4 * 4);
                s = g_nsrc[row];
            }
            v.x *= s; v.y *= s; v.z *= s; v.w *= s;
            *(float4*)&As[r][c4 * 4] = v;
        }
        for (int idx = threadIdx.x; idx < 1024; idx += 256) {
            ((float4*)Ws)[idx] = ((const float4*)(W1 + (size_t)k0 * HD))[idx];
        }
        __syncthreads();

#pragma unroll
        for (int k = 0; k < 64; k++) {
            float a0 = As[ty * 4 + 0][k];
            float a1 = As[ty * 4 + 1][k];
            float a2 = As[ty * 4 + 2][k];
            float a3 = As[ty * 4 + 3][k];
            float4 w = *(float4*)&Ws[k][tx * 4];
            acc[0][0] += a0 * w.x; acc[0][1] += a0 * w.y; acc[0][2] += a0 * w.z; acc[0][3] += a0 * w.w;
            acc[1][0] += a1 * w.x; acc[1][1] += a1 * w.y; acc[1][2] += a1 * w.z; acc[1][3] += a1 * w.w;
            acc[2][0] += a2 * w.x; acc[2][1] += a2 * w.y; acc[2][2] += a2 * w.z; acc[2][3] += a2 * w.w;
            acc[3][0] += a3 * w.x; acc[3][1] += a3 * w.y; acc[3][2] += a3 * w.z; acc[3][3] += a3 * w.w;
        }
        __syncthreads();
    }

#pragma unroll
    for (int i = 0; i < 4; i++) {
        int row = r0 + ty * 4 + i;
        if (row < N) {
            __half2 h0 = __floats2half2_rn(acc[i][0], acc[i][1]);
            __half2 h1 = __floats2half2_rn(acc[i][2], acc[i][3]);
            uint2 pk;
            pk.x = *(unsigned*)&h0;
            pk.y = *(unsigned*)&h1;
            *(uint2*)(g_x16 + (size_t)row * HD + tx * 4) = pk;
        }
    }
}

// ---------------------------------------------------------------------------
// Shuffle-batched gather core: lane loads csr[j+lane] once per 32 edges,
// indices broadcast via shfl -> ~1 LDG per edge (feature row line).
// ---------------------------------------------------------------------------
__device__ __forceinline__ void gather_row(const __half* __restrict__ X,
                                           int beg, int end, int lane,
                                           float& ax, float& ay) {
    ax = 0.f; ay = 0.f;
    int j = beg;
    for (; j + 32 <= end; j += 32) {
        int s = g_csr[j + lane];
#pragma unroll
        for (int t = 0; t < 32; t += 4) {
            int r0 = __shfl_sync(0xffffffffu, s, t + 0);
            int r1 = __shfl_sync(0xffffffffu, s, t + 1);
            int r2 = __shfl_sync(0xffffffffu, s, t + 2);
            int r3 = __shfl_sync(0xffffffffu, s, t + 3);
            float2 v0 = __half22float2(*(const __half2*)(X + (size_t)r0 * HD + lane * 2));
            float2 v1 = __half22float2(*(const __half2*)(X + (size_t)r1 * HD + lane * 2));
            float2 v2 = __half22float2(*(const __half2*)(X + (size_t)r2 * HD + lane * 2));
            float2 v3 = __half22float2(*(const __half2*)(X + (size_t)r3 * HD + lane * 2));
            ax += (v0.x + v1.x) + (v2.x + v3.x);
            ay += (v0.y + v1.y) + (v2.y + v3.y);
        }
    }
    int rem = end - j;
    if (rem > 0) {
        int s = (lane < rem) ? g_csr[j + lane] : 0;
        int t = 0;
        for (; t + 4 <= rem; t += 4) {
            int r0 = __shfl_sync(0xffffffffu, s, t + 0);
            int r1 = __shfl_sync(0xffffffffu, s, t + 1);
            int r2 = __shfl_sync(0xffffffffu, s, t + 2);
            int r3 = __shfl_sync(0xffffffffu, s, t + 3);
            float2 v0 = __half22float2(*(const __half2*)(X + (size_t)r0 * HD + lane * 2));
            float2 v1 = __half22float2(*(const __half2*)(X + (size_t)r1 * HD + lane * 2));
            float2 v2 = __half22float2(*(const __half2*)(X + (size_t)r2 * HD + lane * 2));
            float2 v3 = __half22float2(*(const __half2*)(X + (size_t)r3 * HD + lane * 2));
            ax += (v0.x + v1.x) + (v2.x + v3.x);
            ay += (v0.y + v1.y) + (v2.y + v3.y);
        }
        for (; t < rem; t++) {
            int r = __shfl_sync(0xffffffffu, s, t);
            float2 v = __half22float2(*(const __half2*)(X + (size_t)r * HD + lane * 2));
            ax += v.x; ay += v.y;
        }
    }
}

__global__ void __launch_bounds__(256) gather1_kernel(const float* __restrict__ b1, int N) {
    int warp = (blockIdx.x * blockDim.x + threadIdx.x) >> 5;
    int lane = threadIdx.x & 31;
    if (warp >= N) return;
    int beg = g_off[warp];
    int end = beg + g_cnt[NN + warp];

    float ax, ay;
    gather_row(g_x16, beg, end, lane, ax, ay);

    float nd = g_ndst[warp];
    float ns = g_nsrc[warp];
    float2 b = *(const float2*)(b1 + lane * 2);
    float ox = fmaxf(ax * nd + b.x, 0.f) * ns;
    float oy = fmaxf(ay * nd + b.y, 0.f) * ns;
    *(__half2*)(g_y16 + (size_t)warp * HD + lane * 2) = __floats2half2_rn(ox, oy);
}

__global__ void __launch_bounds__(256) gather2_kernel(int N) {
    int warp = (blockIdx.x * blockDim.x + threadIdx.x) >> 5;
    int lane = threadIdx.x & 31;
    if (warp >= N) return;
    int beg = g_off[warp];
    int end = beg + g_cnt[NN + warp];

    float ax, ay;
    gather_row(g_y16, beg, end, lane, ax, ay);

    float nd = g_ndst[warp];
    *(float2*)(g_a2 + (size_t)warp * HD + lane * 2) = make_float2(ax * nd, ay * nd);
}

// ---------------------------------------------------------------------------
// Final: z = (a@W_mu + b_mu) + noise * exp(a@W_sig + b_sig), a = g_a2
// ---------------------------------------------------------------------------
__global__ void __launch_bounds__(256) final_kernel(const float* __restrict__ noise,
                                                    const float* __restrict__ W_mu,
                                                    const float* __restrict__ b_mu,
                                                    const float* __restrict__ W_sig,
                                                    const float* __restrict__ b_sig,
                                                    float* __restrict__ out, int N) {
    __shared__ float As[64][36];
    __shared__ float Wc[32][128];
    int tx = threadIdx.x & 15, ty = threadIdx.x >> 4;
    int r0 = blockIdx.x * 64;

    float am[4][4] = {};
    float asg[4][4] = {};

    for (int k0 = 0; k0 < HD; k0 += 32) {
        for (int idx = threadIdx.x; idx < 512; idx += 256) {
            int r = idx >> 3;
            int c4 = idx & 7;
            int row = r0 + r;
            float4 v = make_float4(0.f, 0.f, 0.f, 0.f);
            if (row < N) v = *(const float4*)(g_a2 + (size_t)row * HD + k0 + c4 * 4);
            *(float4*)&As[r][c4 * 4] = v;
        }
        for (int idx = threadIdx.x; idx < 1024; idx += 256) {
            int k = idx >> 5;
            int c4 = idx & 31;
            if (c4 < 16) {
                *(float4*)&Wc[k][c4 * 4] = *(const float4*)(W_mu + (size_t)(k0 + k) * HD + c4 * 4);
            } else {
                *(float4*)&Wc[k][64 + (c4 - 16) * 4] =
                    *(const float4*)(W_sig + (size_t)(k0 + k) * HD + (c4 - 16) * 4);
            }
        }
        __syncthreads();

#pragma unroll
        for (int k = 0; k < 32; k++) {
            float a0 = As[ty * 4 + 0][k];
            float a1 = As[ty * 4 + 1][k];
            float a2 = As[ty * 4 + 2][k];
            float a3 = As[ty * 4 + 3][k];
            float4 wm = *(float4*)&Wc[k][tx * 4];
            float4 ws = *(float4*)&Wc[k][64 + tx * 4];
            am[0][0] += a0 * wm.x; am[0][1] += a0 * wm.y; am[0][2] += a0 * wm.z; am[0][3] += a0 * wm.w;
            am[1][0] += a1 * wm.x; am[1][1] += a1 * wm.y; am[1][2] += a1 * wm.z; am[1][3] += a1 * wm.w;
            am[2][0] += a2 * wm.x; am[2][1] += a2 * wm.y; am[2][2] += a2 * wm.z; am[2][3] += a2 * wm.w;
            am[3][0] += a3 * wm.x; am[3][1] += a3 * wm.y; am[3][2] += a3 * wm.z; am[3][3] += a3 * wm.w;
            asg[0][0] += a0 * ws.x; asg[0][1] += a0 * ws.y; asg[0][2] += a0 * ws.z; asg[0][3] += a0 * ws.w;
            asg[1][0] += a1 * ws.x; asg[1][1] += a1 * ws.y; asg[1][2] += a1 * ws.z; asg[1][3] += a1 * ws.w;
            asg[2][0] += a2 * ws.x; asg[2][1] += a2 * ws.y; asg[2][2] += a2 * ws.z; asg[2][3] += a2 * ws.w;
            asg[3][0] += a3 * ws.x; asg[3][1] += a3 * ws.y; asg[3][2] += a3 * ws.z; asg[3][3] += a3 * ws.w;
        }
        __syncthreads();
    }

    float4 bm = *(const float4*)(b_mu + tx * 4);
    float4 bs = *(const float4*)(b_sig + tx * 4);

#pragma unroll
    for (int i = 0; i < 4; i++) {
        int row = r0 + ty * 4 + i;
        if (row < N) {
            float4 nz = *(const float4*)(noise + (size_t)row * HD + tx * 4);
            float4 o;
            o.x = (am[i][0] + bm.x) + nz.x * expf(asg[i][0] + bs.x);
            o.y = (am[i][1] + bm.y) + nz.y * expf(asg[i][1] + bs.y);
            o.z = (am[i][2] + bm.z) + nz.z * expf(asg[i][2] + bs.z);
            o.w = (am[i][3] + bm.w) + nz.w * expf(asg[i][3] + bs.w);
            *(float4*)(out + (size_t)row * HD + tx * 4) = o;
        }
    }
}

// ---------------------------------------------------------------------------
// Launch
// ---------------------------------------------------------------------------
static cudaStream_t s2 = nullptr;
static cudaEvent_t  evScan = nullptr, evGemm = nullptr;

extern "C" void kernel_launch(void* const* d_in, const int* in_sizes, int n_in,
                              void* d_out, int out_size) {
    const float* feat  = (const float*)d_in[0];
    const int*   src   = (const int*)d_in[1];
    const int*   dst   = (const int*)d_in[2];
    const float* noise = (const float*)d_in[3];
    const float* W1    = (const float*)d_in[4];
    const float* b1    = (const float*)d_in[5];
    const float* W_mu  = (const float*)d_in[6];
    const float* b_mu  = (const float*)d_in[7];
    const float* W_sig = (const float*)d_in[8];
    const float* b_sig = (const float*)d_in[9];

    int N = in_sizes[0] / FD;
    int E = in_sizes[1];

    if (s2 == nullptr) {
        cudaStreamCreateWithFlags(&s2, cudaStreamNonBlocking);
        cudaEventCreateWithFlags(&evScan, cudaEventDisableTiming);
        cudaEventCreateWithFlags(&evGemm, cudaEventDisableTiming);
    }

    void* p_cnt;
    cudaGetSymbolAddress(&p_cnt, g_cnt);
    cudaMemsetAsync(p_cnt, 0, sizeof(int) * (2 * NN + 32));     // counts + scan ticket

    deg_kernel<<<(E / 4 + 255) / 256, 256>>>(src, dst, E);
    scan_norm_kernel<<<(N + 255) / 256, 256>>>(N);
    cudaEventRecord(evScan, 0);

    // gemm1 (needs nsrc only) runs concurrently with fill on stream 2
    cudaStreamWaitEvent(s2, evScan, 0);
    gemm1_kernel<<<(N + 63) / 64, 256, 0, s2>>>(feat, W1, N);
    cudaEventRecord(evGemm, s2);

    fill_kernel<<<(E + 255) / 256, 256>>>(src, dst, E);
    cudaStreamWaitEvent(0, evGemm, 0);

    int gblocks = (N * 32 + 255) / 256;
    gather1_kernel<<<gblocks, 256>>>(b1, N);
    gather2_kernel<<<gblocks, 256>>>(N);

    final_kernel<<<(N + 63) / 64, 256>>>(noise, W_mu, b_mu, W_sig, b_sig,
                                         (float*)d_out, N);
}